// round 2
// baseline (speedup 1.0000x reference)
#include <cuda_runtime.h>
#include <cuda_bf16.h>
#include <cstddef>

// Problem constants
#define BB   128     // batch
#define TT   512     // seq len
#define EE   256     // embed dim
#define HH   256     // hidden
#define G4H  1024    // 4*H
#define VV   32000   // vocab
#define NC   32      // classes

// ---------------- device scratch (no allocations allowed) ----------------
__device__ float g_P[(size_t)VV * 2048];          // [V][2*4H]  vocab projection (+bias folded)
__device__ float g_h[2][2][BB][HH];               // [phase][dir][B][H] double-buffered hidden
__device__ float g_hfin[2][BB][HH];               // final hidden per direction
__device__ int   g_bar;                           // grid barrier counter

// ---------------- f32x2 helpers (FFMA2 path, PTX-only) ----------------
__device__ __forceinline__ unsigned long long pack2(float lo, float hi) {
    unsigned long long r;
    asm("mov.b64 %0, {%1, %2};" : "=l"(r) : "f"(lo), "f"(hi));
    return r;
}
__device__ __forceinline__ float2 unpack2(unsigned long long v) {
    float2 r;
    asm("mov.b64 {%0, %1}, %2;" : "=f"(r.x), "=f"(r.y) : "l"(v));
    return r;
}
__device__ __forceinline__ void ffma2(unsigned long long& d, unsigned long long a, unsigned long long b) {
    asm("fma.rn.f32x2 %0, %1, %2, %0;" : "+l"(d) : "l"(a), "l"(b));
}

__device__ __forceinline__ int ld_acq(const int* p) {
    int v;
    asm volatile("ld.acquire.gpu.b32 %0, [%1];" : "=r"(v) : "l"(p));
    return v;
}

__device__ __forceinline__ float sigm(float x) { return 1.0f / (1.0f + expf(-x)); }

// =====================================================================
// Kernel A: P[v, d*1024+g] = sum_e emb[v,e] * W{f,b}[e,g] + b{f,b}[g]
// M=32000, N=2048, K=256.  BM=64, BN=64, BK=16, 256 threads, 4x4/thread (f32x2 cols)
// =====================================================================
__global__ void __launch_bounds__(256) proj_kernel(
    const float* __restrict__ emb,
    const float* __restrict__ Wf, const float* __restrict__ bf,
    const float* __restrict__ Wb, const float* __restrict__ bb)
{
    if (blockIdx.x == 0 && blockIdx.y == 0 && threadIdx.x == 0) g_bar = 0;  // reset barrier for kernel B

    __shared__ float As[16][68];   // [k][m] transposed, padded; row stride 272B (16B aligned)
    __shared__ float Bs[16][64];   // [k][n]

    const int tid = threadIdx.x;
    const int tx = tid & 15, ty = tid >> 4;
    const int m0 = ty * 4, n0 = tx * 4;
    const int vbase = blockIdx.y * 64;
    const int nbase = blockIdx.x * 64;
    const int d = nbase >> 10;                       // 0: fwd, 1: bwd (uniform per CTA)
    const float* W    = d ? Wb : Wf;
    const float* bias = d ? bb : bf;
    const int gbase = nbase & 1023;

    unsigned long long acc[4][2] = {};               // 0ull == two +0.0f

    for (int kt = 0; kt < 256; kt += 16) {
        // load A tile 64x16 (coalesced over e)
        #pragma unroll
        for (int i = tid; i < 1024; i += 256) {
            int row = i >> 4, k = i & 15;
            As[k][row] = emb[(size_t)(vbase + row) * EE + kt + k];
        }
        // load B tile 16x64 (coalesced over g)
        #pragma unroll
        for (int i = tid; i < 1024; i += 256) {
            int k = i >> 6, c = i & 63;
            Bs[k][c] = W[(size_t)(kt + k) * G4H + gbase + c];
        }
        __syncthreads();
        #pragma unroll
        for (int k = 0; k < 16; k++) {
            float4 a4 = *(const float4*)&As[k][m0];
            const unsigned long long* bp = (const unsigned long long*)&Bs[k][n0];
            unsigned long long b0 = bp[0], b1 = bp[1];
            #pragma unroll
            for (int i = 0; i < 4; i++) {
                float av = ((const float*)&a4)[i];
                unsigned long long ad = pack2(av, av);
                ffma2(acc[i][0], ad, b0);
                ffma2(acc[i][1], ad, b1);
            }
        }
        __syncthreads();
    }

    #pragma unroll
    for (int i = 0; i < 4; i++) {
        int v = vbase + m0 + i;
        #pragma unroll
        for (int p = 0; p < 2; p++) {
            float2 va = unpack2(acc[i][p]);
            int c = n0 + 2 * p;
            va.x += bias[gbase + c];
            va.y += bias[gbase + c + 1];
            *(float2*)&g_P[(size_t)v * 2048 + nbase + c] = va;
        }
    }
}

// =====================================================================
// Kernel B: persistent bidirectional LSTM recurrence.
// grid = 128 CTAs (64 per direction), 256 threads.
// CTA (d, s) owns h-columns [4s, 4s+4) -> z-columns {g*256 + 4s + jj}.
// Thread (r = tid&127, half = tid>>7) owns batch row r, h-cols {4s+2*half, +1}.
// U tile (256x16) lives in SMEM for the whole kernel; h broadcast via L2.
// =====================================================================
#define SMEM_B_BYTES ((4096 + 128 * 260) * 4)

__device__ __forceinline__ void gridbar(int target) {
    __syncthreads();
    if (threadIdx.x == 0) {
        __threadfence();
        atomicAdd(&g_bar, 1);
        while (ld_acq(&g_bar) < target) { }
    }
    __syncthreads();
}

__global__ void __launch_bounds__(256) lstm_kernel(
    const int* __restrict__ tokens,
    const float* __restrict__ Uf, const float* __restrict__ Ub)
{
    extern __shared__ float sm[];
    float* Us = sm;               // [256][16]
    float* hs = sm + 4096;        // [128][260]  (pad 260: conflict-free + 16B aligned rows)

    const int tid = threadIdx.x;
    const int d  = blockIdx.x >> 6;
    const int s  = blockIdx.x & 63;
    const int j0 = s * 4;
    const float* U = d ? Ub : Uf;

    // Token dtype guard: jnp.int64 silently downgrades to int32 in JAX unless
    // x64 is enabled. If the buffer IS int64 (LE), every odd 32-bit word of
    // small nonneg values is 0. Random tokens in [0,32000) make a false
    // positive ~1e-18.
    const bool is64 = ((tokens[1] | tokens[3] | tokens[5] | tokens[7]) == 0);
    const int tstride = is64 ? 2 : 1;

    // Preload U tile: Us[k][g*4+jj] = U[k][g*256 + j0 + jj]
    for (int i = tid; i < 4096; i += 256) {
        int k = i >> 4, cc = i & 15;
        int g = cc >> 2, jj = cc & 3;
        Us[k * 16 + cc] = U[(size_t)k * G4H + g * 256 + j0 + jj];
    }

    const int r = tid & 127;
    const int half = tid >> 7;
    const int jj0 = half * 2;

    // zero-init phase-0 hidden slice
    *(float2*)&g_h[0][d][r][j0 + jj0] = make_float2(0.f, 0.f);
    float c0 = 0.f, c1 = 0.f;

    int target = 128;
    gridbar(target);   // all zeros + U tiles visible

    const int* myTok = tokens + (size_t)r * TT * tstride;

    for (int t = 0; t < TT; t++) {
        const int p = t & 1;
        const int te = d ? (TT - 1 - t) : t;
        int tok = myTok[te * tstride];
        tok = (tok >= 0 && tok < VV) ? tok : 0;   // degrade to wrong-answer, never crash

        // stage h (coalesced, L1-bypassing) into padded SMEM
        const float4* src = (const float4*)&g_h[p][d][0][0];
        #pragma unroll 4
        for (int f = tid; f < 8192; f += 256) {
            float4 v = __ldcg(src + f);
            *(float4*)&hs[(f >> 6) * 260 + ((f & 63) << 2)] = v;
        }

        // prefetch input projection for this token (DRAM)
        const float* Prow = g_P + (size_t)tok * 2048 + (size_t)d * G4H + j0 + jj0;
        float2 pv0 = *(const float2*)(Prow);
        float2 pv1 = *(const float2*)(Prow + 256);
        float2 pv2 = *(const float2*)(Prow + 512);
        float2 pv3 = *(const float2*)(Prow + 768);

        __syncthreads();

        unsigned long long acc0 = pack2(pv0.x, pv0.y);
        unsigned long long acc1 = pack2(pv1.x, pv1.y);
        unsigned long long acc2 = pack2(pv2.x, pv2.y);
        unsigned long long acc3 = pack2(pv3.x, pv3.y);

        const float* hrow = &hs[r * 260];
        #pragma unroll 4
        for (int k = 0; k < HH; k += 4) {
            float4 hv = *(const float4*)(hrow + k);
            #pragma unroll
            for (int kk = 0; kk < 4; kk++) {
                float hval = ((const float*)&hv)[kk];
                unsigned long long hd = pack2(hval, hval);
                const float* urow = &Us[(k + kk) * 16 + jj0];
                ffma2(acc0, hd, *(const unsigned long long*)(urow));
                ffma2(acc1, hd, *(const unsigned long long*)(urow + 4));
                ffma2(acc2, hd, *(const unsigned long long*)(urow + 8));
                ffma2(acc3, hd, *(const unsigned long long*)(urow + 12));
            }
        }

        float2 zi = unpack2(acc0), zf = unpack2(acc1);
        float2 zg = unpack2(acc2), zo = unpack2(acc3);

        float i0 = sigm(zi.x), i1 = sigm(zi.y);
        float f0 = sigm(zf.x), f1 = sigm(zf.y);
        float g0 = tanhf(zg.x), g1 = tanhf(zg.y);
        float o0 = sigm(zo.x), o1 = sigm(zo.y);
        c0 = f0 * c0 + i0 * g0;
        c1 = f1 * c1 + i1 * g1;
        float h0 = o0 * tanhf(c0);
        float h1 = o1 * tanhf(c1);

        if (t == TT - 1) {
            *(float2*)&g_hfin[d][r][j0 + jj0] = make_float2(h0, h1);
        } else {
            *(float2*)&g_h[p ^ 1][d][r][j0 + jj0] = make_float2(h0, h1);
            target += 128;
            gridbar(target);
        }
    }
}

// =====================================================================
// Kernel C: head.  h1 = relu([hf|hb] @ W1 + b1); out = softmax(h1 @ W2 + b2)
// grid = 16 CTAs x 8 batch rows, 256 threads.
// =====================================================================
__global__ void __launch_bounds__(256) head_kernel(
    const float* __restrict__ W1, const float* __restrict__ b1,
    const float* __restrict__ W2, const float* __restrict__ b2,
    float* __restrict__ out)
{
    __shared__ float hc[8][512];
    __shared__ float h1[8][256];

    const int tid = threadIdx.x;
    const int rb = blockIdx.x * 8;

    for (int i = tid; i < 4096; i += 256) {
        int rr = i >> 9, k = i & 511;
        int dd = k >> 8, kk = k & 255;
        hc[rr][k] = g_hfin[dd][rb + rr][kk];
    }
    __syncthreads();

    // dense_1: thread = output col j, 8 rows
    const int j = tid;
    float acc[8] = {0.f, 0.f, 0.f, 0.f, 0.f, 0.f, 0.f, 0.f};
    for (int k = 0; k < 512; k++) {
        float w = W1[(size_t)k * HH + j];
        #pragma unroll
        for (int rr = 0; rr < 8; rr++) acc[rr] += hc[rr][k] * w;
    }
    float bj = b1[j];
    #pragma unroll
    for (int rr = 0; rr < 8; rr++) h1[rr][j] = fmaxf(acc[rr] + bj, 0.f);
    __syncthreads();

    // dense_2 + softmax: warp rr handles row rb+rr, lane = class
    const int rr = tid >> 5, c = tid & 31;
    float l = b2[c];
    for (int k = 0; k < HH; k++) l += h1[rr][k] * W2[(size_t)k * NC + c];

    float m = l;
    #pragma unroll
    for (int o = 16; o > 0; o >>= 1) m = fmaxf(m, __shfl_xor_sync(0xffffffffu, m, o));
    float e = expf(l - m);
    float ssum = e;
    #pragma unroll
    for (int o = 16; o > 0; o >>= 1) ssum += __shfl_xor_sync(0xffffffffu, ssum, o);
    out[(size_t)(rb + rr) * NC + c] = e / ssum;
}

// =====================================================================
extern "C" void kernel_launch(void* const* d_in, const int* in_sizes, int n_in,
                              void* d_out, int out_size)
{
    const int*   tokens = (const int*)d_in[0];
    const float* emb = (const float*)d_in[1];
    const float* Wf  = (const float*)d_in[2];
    const float* Uf  = (const float*)d_in[3];
    const float* bf  = (const float*)d_in[4];
    const float* Wb  = (const float*)d_in[5];
    const float* Ub  = (const float*)d_in[6];
    const float* bb  = (const float*)d_in[7];
    const float* W1  = (const float*)d_in[8];
    const float* b1  = (const float*)d_in[9];
    const float* W2  = (const float*)d_in[10];
    const float* b2  = (const float*)d_in[11];
    float* out = (float*)d_out;

    cudaFuncSetAttribute(lstm_kernel, cudaFuncAttributeMaxDynamicSharedMemorySize, SMEM_B_BYTES);

    proj_kernel<<<dim3(32, 500), 256>>>(emb, Wf, bf, Wb, bb);
    lstm_kernel<<<128, 256, SMEM_B_BYTES>>>(tokens, Uf, Ub);
    head_kernel<<<16, 256>>>(W1, b1, W2, b2, out);
}